// round 15
// baseline (speedup 1.0000x reference)
#include <cuda_runtime.h>
#include <cuda_fp16.h>
#include <cstdint>

#define BATCH 4
#define SEQ   2048
#define DIM   1024
#define MROWS (BATCH * SEQ)                    // 8192
#define ATT_ELEMS ((size_t)BATCH * SEQ * SEQ)  // 16,777,216
#define LN_EPS 1e-5f
#define NWORKERS 296                           // 148 SMs x 2 CTAs

// ---------------------------------------------------------------------------
// Scratch (device globals; no allocation allowed anywhere)
// ---------------------------------------------------------------------------
__device__ __align__(256) __half g_xn[MROWS * DIM];
__device__ __align__(256) __half g_q [MROWS * DIM];
__device__ __align__(256) __half g_k [MROWS * DIM];
__device__ __align__(256) __half g_p [ATT_ELEMS];              // fp16 probs
__device__ __align__(256) __half g_wt[3][DIM * DIM];           // W^T fp16 [h][d]
__device__ __align__(256) __half g_vt[(size_t)BATCH * DIM * SEQ]; // V^T [h][n]

// ---------------------------------------------------------------------------
// Helpers
// ---------------------------------------------------------------------------
__device__ __forceinline__ void cp16_s(uint32_t saddr, const void* gmem) {
    asm volatile("cp.async.cg.shared.global [%0], [%1], 16;\n"
                 :: "r"(saddr), "l"(gmem));
}
#define CP_COMMIT() asm volatile("cp.async.commit_group;\n")
#define CP_WAIT(N)  asm volatile("cp.async.wait_group %0;\n" :: "n"(N))

__device__ __forceinline__ void ldsm_x4(
    uint32_t& r0, uint32_t& r1, uint32_t& r2, uint32_t& r3, uint32_t a)
{
    asm volatile("ldmatrix.sync.aligned.m8n8.x4.shared.b16 {%0,%1,%2,%3}, [%4];"
                 : "=r"(r0), "=r"(r1), "=r"(r2), "=r"(r3) : "r"(a));
}
__device__ __forceinline__ void mma16816(
    float* c, const uint32_t* a, const uint32_t* b)
{
    asm volatile(
        "mma.sync.aligned.m16n8k16.row.col.f32.f16.f16.f32 "
        "{%0,%1,%2,%3}, {%4,%5,%6,%7}, {%8,%9}, {%0,%1,%2,%3};"
        : "+f"(c[0]), "+f"(c[1]), "+f"(c[2]), "+f"(c[3])
        : "r"(a[0]), "r"(a[1]), "r"(a[2]), "r"(a[3]), "r"(b[0]), "r"(b[1]));
}

#define SWZ(off) ((off) ^ (((off) >> 3) & 0x70))

// ---------------------------------------------------------------------------
// FP16 mma.sync GEMM tile: C[128,128] = scale*(A@B^T)(+bias)
//   A: [M,K] K-major halves (lda);  B: [N,K] K-major halves (ldb).
//   BK=64 halves (128B rows, SW128), 3-stage cp.async, 128 thr,
//   4 warps (2M x 2N), warp tile 64x64.
//   LDSM addressing: the raw per-lane offset has bits 5-6 == 0 and its swizzle
//   XOR mask depends only on bits 7-9 (invariant under +ks*32 and +s*STG_B).
//   So each address is (unswizzled_base + stage_off + ks*32) ^ mask — the XOR
//   is applied LAST (no carry hazard; identical addresses to the recompute).
//   TRANS: OutT must be __half; result written TRANSPOSED into Cb (V^T path).
// ---------------------------------------------------------------------------
#define TCBM 128
#define TCBN 128
#define TCKT 64
#define NSTG 3
#define ATILE_B (TCBM * 128)              // 16384 bytes
#define BTILE_B (TCBN * 128)              // 16384 bytes
#define STG_B   (ATILE_B + BTILE_B)       // 32768
#define GEMM_SMEM_BYTES (NSTG * STG_B)    // 98304
#define GTHREADS 128
#define LDT 136                           // padded transpose-stage row (halves)

template <bool HAS_BIAS, bool TRANS, typename OutT>
__device__ __forceinline__ void tc_gemm_tile(
    const __half* __restrict__ Ab, const __half* __restrict__ Bb,
    OutT* __restrict__ Cb, const float* __restrict__ bias,
    int K, int lda, int ldb, int ldc, float scale, int bm, int bn)
{
    extern __shared__ char smem[];
    uint32_t sb = (uint32_t)__cvta_generic_to_shared(smem);

    int tid = threadIdx.x, wid = tid >> 5, lane = tid & 31;
    int warpM = wid & 1;            // 0..1  (64 rows)
    int warpN = wid >> 1;           // 0..1  (64 cols)

    int a_row = lane & 15;
    int a_c16 = (lane >> 4) * 16;
    int b_row = (lane & 7) + ((lane >> 4) & 1) * 8;
    int b_c16 = ((lane >> 3) & 1) * 16;

    // Hoisted UNSWIZZLED bases + XOR masks. The raw offsets have bits 5-6 = 0,
    // so +ks*32 never carries and the mask (bits 7-9 of the raw offset) is
    // invariant. Final address = (base + stage + ks*32) ^ mask.
    uint32_t a_base[4], a_mask[4], b_base[4], b_mask[4];
    #pragma unroll
    for (int mi = 0; mi < 4; mi++) {
        uint32_t off = (uint32_t)((warpM * 64 + mi * 16 + a_row) * 128 + a_c16);
        a_mask[mi] = (off >> 3) & 0x70;
        a_base[mi] = sb + off;
    }
    #pragma unroll
    for (int nj = 0; nj < 4; nj++) {
        uint32_t off = (uint32_t)((warpN * 64 + nj * 16 + b_row) * 128 + b_c16);
        b_mask[nj] = (off >> 3) & 0x70;
        b_base[nj] = sb + ATILE_B + off;
    }

    auto load_stage = [&](uint32_t soff, int k0) {
        uint32_t abase = sb + soff;
        uint32_t bbase = abase + ATILE_B;
        #pragma unroll
        for (int i = 0; i < 8; i++) {            // A: 1024 16B chunks
            int c = tid + i * GTHREADS;
            int r = c >> 3, col = c & 7;
            uint32_t off = (uint32_t)(r * 128 + col * 16);
            cp16_s(abase + SWZ(off),
                   Ab + (size_t)(bm + r) * lda + k0 + col * 8);
        }
        #pragma unroll
        for (int i = 0; i < 8; i++) {            // B: 1024 16B chunks
            int c = tid + i * GTHREADS;
            int r = c >> 3, col = c & 7;
            uint32_t off = (uint32_t)(r * 128 + col * 16);
            cp16_s(bbase + SWZ(off),
                   Bb + (size_t)(bn + r) * ldb + k0 + col * 8);
        }
    };

    float acc[4][8][4];
    #pragma unroll
    for (int mi = 0; mi < 4; mi++)
        #pragma unroll
        for (int ni = 0; ni < 8; ni++)
            #pragma unroll
            for (int e = 0; e < 4; e++)
                acc[mi][ni][e] = 0.0f;

    int NT = K / TCKT;

    load_stage(0, 0);
    CP_COMMIT();
    load_stage(STG_B, TCKT);
    CP_COMMIT();

    uint32_t stg_off = 0;                        // current stage offset
    uint32_t ld_off  = 2 * STG_B;                // next load slot offset
    int k0_next = 2 * TCKT;                      // next load k origin

    for (int kt = 0; kt < NT; kt++) {
        CP_WAIT(1);
        __syncthreads();

        if (kt + 2 < NT) load_stage(ld_off, k0_next);
        CP_COMMIT();
        ld_off = (ld_off == (NSTG - 1) * STG_B) ? 0u : ld_off + STG_B;
        k0_next += TCKT;

        uint32_t cur = stg_off;
        stg_off = (stg_off == (NSTG - 1) * STG_B) ? 0u : stg_off + STG_B;

        #pragma unroll
        for (int ks = 0; ks < 4; ks++) {         // 4 x k16 = K-tile 64
            uint32_t a[4][4], b[8][2];
            #pragma unroll
            for (int mi = 0; mi < 4; mi++)
                ldsm_x4(a[mi][0], a[mi][1], a[mi][2], a[mi][3],
                        (a_base[mi] + cur + ks * 32) ^ a_mask[mi]);
            #pragma unroll
            for (int nj = 0; nj < 4; nj++)
                ldsm_x4(b[2 * nj][0], b[2 * nj][1],
                        b[2 * nj + 1][0], b[2 * nj + 1][1],
                        (b_base[nj] + cur + ks * 32) ^ b_mask[nj]);
            #pragma unroll
            for (int mi = 0; mi < 4; mi++)
                #pragma unroll
                for (int ni = 0; ni < 8; ni++)
                    mma16816(acc[mi][ni], a[mi], b[ni]);
        }
    }

    int g = lane >> 2, t = lane & 3;

    if constexpr (TRANS) {
        // Stage result in smem transposed ([col][row], padded), then write
        // coalesced rows of V^T. Requires OutT == __half.
        __half* st = reinterpret_cast<__half*>(smem);
        __syncthreads();   // smem stages are dead; safe to reuse
        #pragma unroll
        for (int mi = 0; mi < 4; mi++) {
            int r0 = warpM * 64 + mi * 16 + g;
            #pragma unroll
            for (int ni = 0; ni < 8; ni++) {
                int col = warpN * 64 + ni * 8 + 2 * t;
                float v0 = acc[mi][ni][0] * scale;
                float v1 = acc[mi][ni][1] * scale;
                float v2 = acc[mi][ni][2] * scale;
                float v3 = acc[mi][ni][3] * scale;
                if (HAS_BIAS) {
                    float b0 = bias[bn + col], b1 = bias[bn + col + 1];
                    v0 += b0; v1 += b1; v2 += b0; v3 += b1;
                }
                st[col * LDT + r0]           = __float2half_rn(v0);
                st[(col + 1) * LDT + r0]     = __float2half_rn(v1);
                st[col * LDT + r0 + 8]       = __float2half_rn(v2);
                st[(col + 1) * LDT + r0 + 8] = __float2half_rn(v3);
            }
        }
        __syncthreads();
        int b = bm >> 11;                 // SEQ = 2048
        int nb = bm & (SEQ - 1);
        __half* dst = (__half*)Cb + ((size_t)b * DIM + bn + tid) * SEQ + nb;
        const uint4* src = reinterpret_cast<const uint4*>(st + tid * LDT);
        #pragma unroll
        for (int i = 0; i < 16; i++)
            reinterpret_cast<uint4*>(dst)[i] = src[i];
        __syncthreads();
        return;
    }

    // Register epilogue: c0,c1 -> (row g, col 2t); c2,c3 -> (row g+8)
    #pragma unroll
    for (int mi = 0; mi < 4; mi++) {
        int r0 = bm + warpM * 64 + mi * 16 + g;
        #pragma unroll
        for (int ni = 0; ni < 8; ni++) {
            int col = bn + warpN * 64 + ni * 8 + 2 * t;
            float2 lo, hi;
            lo.x = acc[mi][ni][0] * scale; lo.y = acc[mi][ni][1] * scale;
            hi.x = acc[mi][ni][2] * scale; hi.y = acc[mi][ni][3] * scale;
            if (HAS_BIAS) {
                float b0 = bias[col], b1 = bias[col + 1];
                lo.x += b0; lo.y += b1; hi.x += b0; hi.y += b1;
            }
            if (sizeof(OutT) == 2) {
                *reinterpret_cast<__half2*>(
                    (__half*)Cb + (size_t)r0 * ldc + col) =
                    __floats2half2_rn(lo.x, lo.y);
                *reinterpret_cast<__half2*>(
                    (__half*)Cb + (size_t)(r0 + 8) * ldc + col) =
                    __floats2half2_rn(hi.x, hi.y);
            } else {
                *reinterpret_cast<float2*>(
                    (float*)Cb + (size_t)r0 * ldc + col) = lo;
                *reinterpret_cast<float2*>(
                    (float*)Cb + (size_t)(r0 + 8) * ldc + col) = hi;
            }
        }
    }
    __syncthreads();   // protect smem stages before next tile's prologue
}

// ---------------------------------------------------------------------------
// Persistent GEMM kernels (static scheduling; V tiles first)
// ---------------------------------------------------------------------------
__global__ __launch_bounds__(GTHREADS, 2) void qkv_kernel(
    const __half* __restrict__ xn,
    const float* __restrict__ b0, const float* __restrict__ b1,
    const float* __restrict__ b2,
    __half* q, __half* k, __half* vt)
{
    const int TPM = MROWS / TCBM;      // 64
    const int TPN = DIM / TCBN;        // 8
    const int TPZ = TPM * TPN;         // 512
    const int NTILES = 3 * TPZ;        // 1536; order: V(0..511), Q, K
    for (int t = blockIdx.x; t < NTILES; t += gridDim.x) {
        int zz = t / TPZ, rem = t - zz * TPZ;
        int bm = (rem / TPN) * TCBM;
        int bn = (rem - (rem / TPN) * TPN) * TCBN;
        if (zz == 0) {
            tc_gemm_tile<true, true, __half>(xn, g_wt[2], vt, b2,
                                             DIM, DIM, DIM, SEQ, 1.0f, bm, bn);
        } else if (zz == 1) {
            tc_gemm_tile<true, false, __half>(xn, g_wt[0], q, b0,
                                              DIM, DIM, DIM, DIM, 1.0f, bm, bn);
        } else {
            tc_gemm_tile<true, false, __half>(xn, g_wt[1], k, b1,
                                              DIM, DIM, DIM, DIM, 1.0f, bm, bn);
        }
    }
}

__global__ __launch_bounds__(GTHREADS, 2) void scores_kernel(
    const __half* __restrict__ q, const __half* __restrict__ k,
    float* __restrict__ att)
{
    const int TPM = SEQ / TCBM;        // 16
    const int TPN = SEQ / TCBN;        // 16
    const int TPZ = TPM * TPN;         // 256
    const int NTILES = BATCH * TPZ;    // 1024
    for (int t = blockIdx.x; t < NTILES; t += gridDim.x) {
        int z = t / TPZ, rem = t - z * TPZ;
        int bm = (rem / TPN) * TCBM;
        int bn = (rem - (rem / TPN) * TPN) * TCBN;
        size_t zo = (size_t)z * SEQ * DIM;
        float* Cb = att + (size_t)z * SEQ * SEQ;
        tc_gemm_tile<false, false, float>(q + zo, k + zo, Cb, nullptr,
                                          DIM, DIM, DIM, SEQ, 1.0f / 32.0f,
                                          bm, bn);
    }
}

__global__ __launch_bounds__(GTHREADS, 2) void attv_kernel(
    const __half* __restrict__ p, const __half* __restrict__ vt,
    float* __restrict__ out)
{
    const int TPM = SEQ / TCBM;        // 16
    const int TPN = DIM / TCBN;        // 8
    const int TPZ = TPM * TPN;         // 128
    const int NTILES = BATCH * TPZ;    // 512
    for (int t = blockIdx.x; t < NTILES; t += gridDim.x) {
        int z = t / TPZ, rem = t - z * TPZ;
        int bm = (rem / TPN) * TCBM;
        int bn = (rem - (rem / TPN) * TPN) * TCBN;
        const __half* Ab = p  + (size_t)z * SEQ * SEQ;
        const __half* Bb = vt + (size_t)z * DIM * SEQ;
        float* Cb = out + (size_t)z * SEQ * DIM;
        tc_gemm_tile<false, false, float>(Ab, Bb, Cb, nullptr,
                                          SEQ, SEQ, SEQ, DIM, 1.0f, bm, bn);
    }
}

// ---------------------------------------------------------------------------
// W transpose (fp32 [d][h] -> fp16 [h][d])
// ---------------------------------------------------------------------------
__global__ __launch_bounds__(256) void transpose_w_kernel(
    const float* __restrict__ w0, const float* __restrict__ w1,
    const float* __restrict__ w2)
{
    __shared__ float t[32][33];
    int z = blockIdx.z;
    const float* src = (z == 0) ? w0 : (z == 1) ? w1 : w2;  // [d][h]
    __half* dst = g_wt[z];                                  // [h][d]
    int c0 = blockIdx.x * 32;   // h
    int r0 = blockIdx.y * 32;   // d
    int tx = threadIdx.x, ty = threadIdx.y;
    #pragma unroll
    for (int j = 0; j < 4; j++)
        t[ty + j * 8][tx] = src[(size_t)(r0 + ty + j * 8) * DIM + c0 + tx];
    __syncthreads();
    #pragma unroll
    for (int j = 0; j < 4; j++)
        dst[(size_t)(c0 + ty + j * 8) * DIM + r0 + tx] =
            __float2half_rn(t[tx][ty + j * 8]);
}

// ---------------------------------------------------------------------------
// LayerNorm (outputs fp16)
// ---------------------------------------------------------------------------
__global__ __launch_bounds__(256) void ln_kernel(
    const float* __restrict__ x, const float* __restrict__ w,
    const float* __restrict__ b, __half* __restrict__ out)
{
    int row = blockIdx.x;
    int t = threadIdx.x;
    const float4* xr = reinterpret_cast<const float4*>(x + (size_t)row * DIM);
    float4 v = xr[t];

    float s  = v.x + v.y + v.z + v.w;
    float s2 = v.x * v.x + v.y * v.y + v.z * v.z + v.w * v.w;

    __shared__ float red0[32], red1[32];
    #pragma unroll
    for (int o = 16; o > 0; o >>= 1) {
        s  += __shfl_xor_sync(0xFFFFFFFFu, s,  o);
        s2 += __shfl_xor_sync(0xFFFFFFFFu, s2, o);
    }
    int wid = t >> 5, lane = t & 31;
    if (lane == 0) { red0[wid] = s; red1[wid] = s2; }
    __syncthreads();
    if (wid == 0) {
        float a  = (lane < 8) ? red0[lane] : 0.0f;
        float a2 = (lane < 8) ? red1[lane] : 0.0f;
        #pragma unroll
        for (int o = 4; o > 0; o >>= 1) {
            a  += __shfl_xor_sync(0xFFFFFFFFu, a,  o);
            a2 += __shfl_xor_sync(0xFFFFFFFFu, a2, o);
        }
        if (lane == 0) { red0[0] = a * (1.0f / DIM); red1[0] = a2 * (1.0f / DIM); }
    }
    __syncthreads();
    float mu  = red0[0];
    float var = red1[0] - mu * mu;
    float inv = rsqrtf(var + LN_EPS);

    float4 w4 = reinterpret_cast<const float4*>(w)[t];
    float4 b4 = reinterpret_cast<const float4*>(b)[t];
    __half2 h0 = __floats2half2_rn((v.x - mu) * inv * w4.x + b4.x,
                                   (v.y - mu) * inv * w4.y + b4.y);
    __half2 h1 = __floats2half2_rn((v.z - mu) * inv * w4.z + b4.z,
                                   (v.w - mu) * inv * w4.w + b4.w);
    __half2* orow = reinterpret_cast<__half2*>(out + (size_t)row * DIM);
    orow[2 * t]     = h0;
    orow[2 * t + 1] = h1;
}

// ---------------------------------------------------------------------------
// Softmax: exact fp32 -> att (in place), fp16 -> p
// ---------------------------------------------------------------------------
__global__ __launch_bounds__(256) void softmax_kernel(
    float* __restrict__ att, __half* __restrict__ pr)
{
    int row = blockIdx.x;
    float* p  = att + (size_t)row * SEQ;
    __half2* pq = reinterpret_cast<__half2*>(pr + (size_t)row * SEQ);
    int t = threadIdx.x;

    float4 v0 = reinterpret_cast<float4*>(p)[t];
    float4 v1 = reinterpret_cast<float4*>(p)[t + 256];

    float m = fmaxf(fmaxf(fmaxf(v0.x, v0.y), fmaxf(v0.z, v0.w)),
                    fmaxf(fmaxf(v1.x, v1.y), fmaxf(v1.z, v1.w)));

    __shared__ float red[32];
    #pragma unroll
    for (int o = 16; o > 0; o >>= 1)
        m = fmaxf(m, __shfl_xor_sync(0xFFFFFFFFu, m, o));
    int wid = t >> 5, lane = t & 31;
    if (lane == 0) red[wid] = m;
    __syncthreads();
    if (wid == 0) {
        float a = (lane < 8) ? red[lane] : -3.4e38f;
        #pragma unroll
        for (int o = 4; o > 0; o >>= 1)
            a = fmaxf(a, __shfl_xor_sync(0xFFFFFFFFu, a, o));
        if (lane == 0) red[0] = a;
    }
    __syncthreads();
    m = red[0];

    v0.x = __expf(v0.x - m); v0.y = __expf(v0.y - m);
    v0.z = __expf(v0.z - m); v0.w = __expf(v0.w - m);
    v1.x = __expf(v1.x - m); v1.y = __expf(v1.y - m);
    v1.z = __expf(v1.z - m); v1.w = __expf(v1.w - m);

    float s = v0.x + v0.y + v0.z + v0.w + v1.x + v1.y + v1.z + v1.w;
    #pragma unroll
    for (int o = 16; o > 0; o >>= 1)
        s += __shfl_xor_sync(0xFFFFFFFFu, s, o);
    if (lane == 0) red[wid] = s;
    __syncthreads();
    if (wid == 0) {
        float a = (lane < 8) ? red[lane] : 0.0f;
        #pragma unroll
        for (int o = 4; o > 0; o >>= 1)
            a += __shfl_xor_sync(0xFFFFFFFFu, a, o);
        if (lane == 0) red[0] = a;
    }
    __syncthreads();
    float inv = 1.0f / red[0];

    v0.x *= inv; v0.y *= inv; v0.z *= inv; v0.w *= inv;
    v1.x *= inv; v1.y *= inv; v1.z *= inv; v1.w *= inv;
    reinterpret_cast<float4*>(p)[t]       = v0;
    reinterpret_cast<float4*>(p)[t + 256] = v1;

    pq[2 * t]           = __floats2half2_rn(v0.x, v0.y);
    pq[2 * t + 1]       = __floats2half2_rn(v0.z, v0.w);
    pq[2 * (t + 256)]     = __floats2half2_rn(v1.x, v1.y);
    pq[2 * (t + 256) + 1] = __floats2half2_rn(v1.z, v1.w);
}

// ---------------------------------------------------------------------------
// Launch
// ---------------------------------------------------------------------------
extern "C" void kernel_launch(void* const* d_in, const int* in_sizes, int n_in,
                              void* d_out, int out_size)
{
    (void)in_sizes; (void)n_in; (void)out_size;
    const float* x   = (const float*)d_in[0];
    const float* wq  = (const float*)d_in[1];
    const float* bq  = (const float*)d_in[2];
    const float* wk  = (const float*)d_in[3];
    const float* bk  = (const float*)d_in[4];
    const float* wv  = (const float*)d_in[5];
    const float* bv  = (const float*)d_in[6];
    const float* lnw = (const float*)d_in[7];
    const float* lnb = (const float*)d_in[8];

    float* att = (float*)d_out;                 // [4,2048,2048]
    float* out = att + ATT_ELEMS;               // [4,2048,1024]

    __half *xn, *q, *k, *p, *vt;
    cudaGetSymbolAddress((void**)&xn, g_xn);
    cudaGetSymbolAddress((void**)&q,  g_q);
    cudaGetSymbolAddress((void**)&k,  g_k);
    cudaGetSymbolAddress((void**)&p,  g_p);
    cudaGetSymbolAddress((void**)&vt, g_vt);

    cudaFuncSetAttribute(qkv_kernel,
        cudaFuncAttributeMaxDynamicSharedMemorySize, GEMM_SMEM_BYTES);
    cudaFuncSetAttribute(scores_kernel,
        cudaFuncAttributeMaxDynamicSharedMemorySize, GEMM_SMEM_BYTES);
    cudaFuncSetAttribute(attv_kernel,
        cudaFuncAttributeMaxDynamicSharedMemorySize, GEMM_SMEM_BYTES);

    // 0) W^T -> fp16
    transpose_w_kernel<<<dim3(32, 32, 3), dim3(32, 8)>>>(wq, wk, wv);

    // 1) LayerNorm -> fp16 xn
    ln_kernel<<<MROWS, 256>>>(x, lnw, lnb, xn);

    // 2) QKV (q,k normal; V written directly transposed into vt, V first)
    qkv_kernel<<<NWORKERS, GTHREADS, GEMM_SMEM_BYTES>>>(xn, bq, bk, bv, q, k, vt);

    // 3) Scores: att[b] = (q[b] @ k[b]^T) / 32  (fp32 out)
    scores_kernel<<<NWORKERS, GTHREADS, GEMM_SMEM_BYTES>>>(q, k, att);

    // 4) Softmax (exact fp32 -> att, fp16 -> p)
    softmax_kernel<<<MROWS, 256>>>(att, p);

    // 5) out[b] = p[b] @ v[b]  (fp32 out)
    attv_kernel<<<NWORKERS, GTHREADS, GEMM_SMEM_BYTES>>>(p, vt, out);
}

// round 16
// speedup vs baseline: 1.0215x; 1.0215x over previous
#include <cuda_runtime.h>
#include <cuda_fp16.h>
#include <cstdint>

#define BATCH 4
#define SEQ   2048
#define DIM   1024
#define MROWS (BATCH * SEQ)                    // 8192
#define ATT_ELEMS ((size_t)BATCH * SEQ * SEQ)  // 16,777,216
#define LN_EPS 1e-5f

// ---------------------------------------------------------------------------
// Scratch (device globals; no allocation allowed anywhere)
// ---------------------------------------------------------------------------
__device__ __align__(256) __half g_xn[MROWS * DIM];
__device__ __align__(256) __half g_q [MROWS * DIM];
__device__ __align__(256) __half g_k [MROWS * DIM];
__device__ __align__(256) __half g_p [ATT_ELEMS];              // fp16 probs
__device__ __align__(256) __half g_wt[3][DIM * DIM];           // W^T fp16 [h][d]
__device__ __align__(256) __half g_vt[(size_t)BATCH * DIM * SEQ]; // V^T [h][n]

// ---------------------------------------------------------------------------
// Helpers
// ---------------------------------------------------------------------------
__device__ __forceinline__ void cp16_s(uint32_t saddr, const void* gmem) {
    asm volatile("cp.async.cg.shared.global [%0], [%1], 16;\n"
                 :: "r"(saddr), "l"(gmem));
}
#define CP_COMMIT() asm volatile("cp.async.commit_group;\n")
#define CP_WAIT(N)  asm volatile("cp.async.wait_group %0;\n" :: "n"(N))

__device__ __forceinline__ void ldsm_x4(
    uint32_t& r0, uint32_t& r1, uint32_t& r2, uint32_t& r3, uint32_t a)
{
    asm volatile("ldmatrix.sync.aligned.m8n8.x4.shared.b16 {%0,%1,%2,%3}, [%4];"
                 : "=r"(r0), "=r"(r1), "=r"(r2), "=r"(r3) : "r"(a));
}
__device__ __forceinline__ void mma16816(
    float* c, const uint32_t* a, const uint32_t* b)
{
    asm volatile(
        "mma.sync.aligned.m16n8k16.row.col.f32.f16.f16.f32 "
        "{%0,%1,%2,%3}, {%4,%5,%6,%7}, {%8,%9}, {%0,%1,%2,%3};"
        : "+f"(c[0]), "+f"(c[1]), "+f"(c[2]), "+f"(c[3])
        : "r"(a[0]), "r"(a[1]), "r"(a[2]), "r"(a[3]), "r"(b[0]), "r"(b[1]));
}

#define SWZ(off) ((off) ^ (((off) >> 3) & 0x70))

// ---------------------------------------------------------------------------
// FP16 mma.sync GEMM tile: C[128,128] = scale*(A@B^T)(+bias)
//   A: [M,K] K-major halves (lda);  B: [N,K] K-major halves (ldb).
//   BK=64 halves (128B rows, SW128), 3-stage cp.async, 128 thr,
//   4 warps (2M x 2N), warp tile 64x64.
//   LDSM addressing: raw per-lane offset has bits 5-6 == 0; its swizzle XOR
//   mask depends only on bits 7-9 (invariant under +ks*32 and +s*STG_B).
//   Address = (unswizzled_base + stage_off + ks*32) ^ mask (XOR applied last).
//   TRANS: OutT must be __half; result written TRANSPOSED into Cb (V^T path).
// ---------------------------------------------------------------------------
#define TCBM 128
#define TCBN 128
#define TCKT 64
#define NSTG 3
#define ATILE_B (TCBM * 128)              // 16384 bytes
#define BTILE_B (TCBN * 128)              // 16384 bytes
#define STG_B   (ATILE_B + BTILE_B)       // 32768
#define GEMM_SMEM_BYTES (NSTG * STG_B)    // 98304
#define GTHREADS 128
#define LDT 136                           // padded transpose-stage row (halves)

template <bool HAS_BIAS, bool TRANS, typename OutT>
__device__ __forceinline__ void tc_gemm_tile(
    const __half* __restrict__ Ab, const __half* __restrict__ Bb,
    OutT* __restrict__ Cb, const float* __restrict__ bias,
    int K, int lda, int ldb, int ldc, float scale, int bm, int bn)
{
    extern __shared__ char smem[];
    uint32_t sb = (uint32_t)__cvta_generic_to_shared(smem);

    int tid = threadIdx.x, wid = tid >> 5, lane = tid & 31;
    int warpM = wid & 1;            // 0..1  (64 rows)
    int warpN = wid >> 1;           // 0..1  (64 cols)

    int a_row = lane & 15;
    int a_c16 = (lane >> 4) * 16;
    int b_row = (lane & 7) + ((lane >> 4) & 1) * 8;
    int b_c16 = ((lane >> 3) & 1) * 16;

    // Hoisted unswizzled bases + XOR masks.
    uint32_t a_base[4], a_mask[4], b_base[4], b_mask[4];
    #pragma unroll
    for (int mi = 0; mi < 4; mi++) {
        uint32_t off = (uint32_t)((warpM * 64 + mi * 16 + a_row) * 128 + a_c16);
        a_mask[mi] = (off >> 3) & 0x70;
        a_base[mi] = sb + off;
    }
    #pragma unroll
    for (int nj = 0; nj < 4; nj++) {
        uint32_t off = (uint32_t)((warpN * 64 + nj * 16 + b_row) * 128 + b_c16);
        b_mask[nj] = (off >> 3) & 0x70;
        b_base[nj] = sb + ATILE_B + off;
    }

    auto load_stage = [&](uint32_t soff, int k0) {
        uint32_t abase = sb + soff;
        uint32_t bbase = abase + ATILE_B;
        #pragma unroll
        for (int i = 0; i < 8; i++) {            // A: 1024 16B chunks
            int c = tid + i * GTHREADS;
            int r = c >> 3, col = c & 7;
            uint32_t off = (uint32_t)(r * 128 + col * 16);
            cp16_s(abase + SWZ(off),
                   Ab + (size_t)(bm + r) * lda + k0 + col * 8);
        }
        #pragma unroll
        for (int i = 0; i < 8; i++) {            // B: 1024 16B chunks
            int c = tid + i * GTHREADS;
            int r = c >> 3, col = c & 7;
            uint32_t off = (uint32_t)(r * 128 + col * 16);
            cp16_s(bbase + SWZ(off),
                   Bb + (size_t)(bn + r) * ldb + k0 + col * 8);
        }
    };

    float acc[4][8][4];
    #pragma unroll
    for (int mi = 0; mi < 4; mi++)
        #pragma unroll
        for (int ni = 0; ni < 8; ni++)
            #pragma unroll
            for (int e = 0; e < 4; e++)
                acc[mi][ni][e] = 0.0f;

    int NT = K / TCKT;

    load_stage(0, 0);
    CP_COMMIT();
    load_stage(STG_B, TCKT);
    CP_COMMIT();

    uint32_t stg_off = 0;                        // current stage offset
    uint32_t ld_off  = 2 * STG_B;                // next load slot offset
    int k0_next = 2 * TCKT;                      // next load k origin

    for (int kt = 0; kt < NT; kt++) {
        CP_WAIT(1);
        __syncthreads();

        if (kt + 2 < NT) load_stage(ld_off, k0_next);
        CP_COMMIT();
        ld_off = (ld_off == (NSTG - 1) * STG_B) ? 0u : ld_off + STG_B;
        k0_next += TCKT;

        uint32_t cur = stg_off;
        stg_off = (stg_off == (NSTG - 1) * STG_B) ? 0u : stg_off + STG_B;

        #pragma unroll
        for (int ks = 0; ks < 4; ks++) {         // 4 x k16 = K-tile 64
            uint32_t a[4][4], b[8][2];
            #pragma unroll
            for (int mi = 0; mi < 4; mi++)
                ldsm_x4(a[mi][0], a[mi][1], a[mi][2], a[mi][3],
                        (a_base[mi] + cur + ks * 32) ^ a_mask[mi]);
            #pragma unroll
            for (int nj = 0; nj < 4; nj++)
                ldsm_x4(b[2 * nj][0], b[2 * nj][1],
                        b[2 * nj + 1][0], b[2 * nj + 1][1],
                        (b_base[nj] + cur + ks * 32) ^ b_mask[nj]);
            #pragma unroll
            for (int mi = 0; mi < 4; mi++)
                #pragma unroll
                for (int ni = 0; ni < 8; ni++)
                    mma16816(acc[mi][ni], a[mi], b[ni]);
        }
    }

    int g = lane >> 2, t = lane & 3;

    if constexpr (TRANS) {
        // Stage result in smem transposed ([col][row], padded), then write
        // coalesced rows of V^T. Requires OutT == __half.
        __half* st = reinterpret_cast<__half*>(smem);
        __syncthreads();   // smem stages are dead; safe to reuse
        #pragma unroll
        for (int mi = 0; mi < 4; mi++) {
            int r0 = warpM * 64 + mi * 16 + g;
            #pragma unroll
            for (int ni = 0; ni < 8; ni++) {
                int col = warpN * 64 + ni * 8 + 2 * t;
                float v0 = acc[mi][ni][0] * scale;
                float v1 = acc[mi][ni][1] * scale;
                float v2 = acc[mi][ni][2] * scale;
                float v3 = acc[mi][ni][3] * scale;
                if (HAS_BIAS) {
                    float b0 = bias[bn + col], b1 = bias[bn + col + 1];
                    v0 += b0; v1 += b1; v2 += b0; v3 += b1;
                }
                st[col * LDT + r0]           = __float2half_rn(v0);
                st[(col + 1) * LDT + r0]     = __float2half_rn(v1);
                st[col * LDT + r0 + 8]       = __float2half_rn(v2);
                st[(col + 1) * LDT + r0 + 8] = __float2half_rn(v3);
            }
        }
        __syncthreads();
        int b = bm >> 11;                 // SEQ = 2048
        int nb = bm & (SEQ - 1);
        __half* dst = (__half*)Cb + ((size_t)b * DIM + bn + tid) * SEQ + nb;
        const uint4* src = reinterpret_cast<const uint4*>(st + tid * LDT);
        #pragma unroll
        for (int i = 0; i < 16; i++)
            reinterpret_cast<uint4*>(dst)[i] = src[i];
        return;
    }

    // Register epilogue: c0,c1 -> (row g, col 2t); c2,c3 -> (row g+8)
    #pragma unroll
    for (int mi = 0; mi < 4; mi++) {
        int r0 = bm + warpM * 64 + mi * 16 + g;
        #pragma unroll
        for (int ni = 0; ni < 8; ni++) {
            int col = bn + warpN * 64 + ni * 8 + 2 * t;
            float2 lo, hi;
            lo.x = acc[mi][ni][0] * scale; lo.y = acc[mi][ni][1] * scale;
            hi.x = acc[mi][ni][2] * scale; hi.y = acc[mi][ni][3] * scale;
            if (HAS_BIAS) {
                float b0 = bias[col], b1 = bias[col + 1];
                lo.x += b0; lo.y += b1; hi.x += b0; hi.y += b1;
            }
            if (sizeof(OutT) == 2) {
                *reinterpret_cast<__half2*>(
                    (__half*)Cb + (size_t)r0 * ldc + col) =
                    __floats2half2_rn(lo.x, lo.y);
                *reinterpret_cast<__half2*>(
                    (__half*)Cb + (size_t)(r0 + 8) * ldc + col) =
                    __floats2half2_rn(hi.x, hi.y);
            } else {
                *reinterpret_cast<float2*>(
                    (float*)Cb + (size_t)r0 * ldc + col) = lo;
                *reinterpret_cast<float2*>(
                    (float*)Cb + (size_t)(r0 + 8) * ldc + col) = hi;
            }
        }
    }
}

// ---------------------------------------------------------------------------
// GEMM kernels: one tile per CTA (hardware scheduler balances SM load)
// ---------------------------------------------------------------------------
__global__ __launch_bounds__(GTHREADS, 2) void qkv_kernel(
    const __half* __restrict__ xn,
    const float* __restrict__ b0, const float* __restrict__ b1,
    const float* __restrict__ b2,
    __half* q, __half* k, __half* vt)
{
    const int TPM = MROWS / TCBM;      // 64
    const int TPN = DIM / TCBN;        // 8
    const int TPZ = TPM * TPN;         // 512
    int t = blockIdx.x;                // 0..1535; order: V(0..511), Q, K
    int zz = t / TPZ, rem = t - zz * TPZ;
    int bm = (rem / TPN) * TCBM;
    int bn = (rem - (rem / TPN) * TPN) * TCBN;
    if (zz == 0) {
        tc_gemm_tile<true, true, __half>(xn, g_wt[2], vt, b2,
                                         DIM, DIM, DIM, SEQ, 1.0f, bm, bn);
    } else if (zz == 1) {
        tc_gemm_tile<true, false, __half>(xn, g_wt[0], q, b0,
                                          DIM, DIM, DIM, DIM, 1.0f, bm, bn);
    } else {
        tc_gemm_tile<true, false, __half>(xn, g_wt[1], k, b1,
                                          DIM, DIM, DIM, DIM, 1.0f, bm, bn);
    }
}

__global__ __launch_bounds__(GTHREADS, 2) void scores_kernel(
    const __half* __restrict__ q, const __half* __restrict__ k,
    float* __restrict__ att)
{
    const int TPM = SEQ / TCBM;        // 16
    const int TPN = SEQ / TCBN;        // 16
    const int TPZ = TPM * TPN;         // 256
    int t = blockIdx.x;                // 0..1023
    int z = t / TPZ, rem = t - z * TPZ;
    int bm = (rem / TPN) * TCBM;
    int bn = (rem - (rem / TPN) * TPN) * TCBN;
    size_t zo = (size_t)z * SEQ * DIM;
    float* Cb = att + (size_t)z * SEQ * SEQ;
    tc_gemm_tile<false, false, float>(q + zo, k + zo, Cb, nullptr,
                                      DIM, DIM, DIM, SEQ, 1.0f / 32.0f,
                                      bm, bn);
}

__global__ __launch_bounds__(GTHREADS, 2) void attv_kernel(
    const __half* __restrict__ p, const __half* __restrict__ vt,
    float* __restrict__ out)
{
    const int TPM = SEQ / TCBM;        // 16
    const int TPN = DIM / TCBN;        // 8
    const int TPZ = TPM * TPN;         // 128
    int t = blockIdx.x;                // 0..511
    int z = t / TPZ, rem = t - z * TPZ;
    int bm = (rem / TPN) * TCBM;
    int bn = (rem - (rem / TPN) * TPN) * TCBN;
    const __half* Ab = p  + (size_t)z * SEQ * SEQ;
    const __half* Bb = vt + (size_t)z * DIM * SEQ;
    float* Cb = out + (size_t)z * SEQ * DIM;
    tc_gemm_tile<false, false, float>(Ab, Bb, Cb, nullptr,
                                      SEQ, SEQ, SEQ, DIM, 1.0f, bm, bn);
}

// ---------------------------------------------------------------------------
// W transpose (fp32 [d][h] -> fp16 [h][d])
// ---------------------------------------------------------------------------
__global__ __launch_bounds__(256) void transpose_w_kernel(
    const float* __restrict__ w0, const float* __restrict__ w1,
    const float* __restrict__ w2)
{
    __shared__ float t[32][33];
    int z = blockIdx.z;
    const float* src = (z == 0) ? w0 : (z == 1) ? w1 : w2;  // [d][h]
    __half* dst = g_wt[z];                                  // [h][d]
    int c0 = blockIdx.x * 32;   // h
    int r0 = blockIdx.y * 32;   // d
    int tx = threadIdx.x, ty = threadIdx.y;
    #pragma unroll
    for (int j = 0; j < 4; j++)
        t[ty + j * 8][tx] = src[(size_t)(r0 + ty + j * 8) * DIM + c0 + tx];
    __syncthreads();
    #pragma unroll
    for (int j = 0; j < 4; j++)
        dst[(size_t)(c0 + ty + j * 8) * DIM + r0 + tx] =
            __float2half_rn(t[tx][ty + j * 8]);
}

// ---------------------------------------------------------------------------
// LayerNorm (outputs fp16)
// ---------------------------------------------------------------------------
__global__ __launch_bounds__(256) void ln_kernel(
    const float* __restrict__ x, const float* __restrict__ w,
    const float* __restrict__ b, __half* __restrict__ out)
{
    int row = blockIdx.x;
    int t = threadIdx.x;
    const float4* xr = reinterpret_cast<const float4*>(x + (size_t)row * DIM);
    float4 v = xr[t];

    float s  = v.x + v.y + v.z + v.w;
    float s2 = v.x * v.x + v.y * v.y + v.z * v.z + v.w * v.w;

    __shared__ float red0[32], red1[32];
    #pragma unroll
    for (int o = 16; o > 0; o >>= 1) {
        s  += __shfl_xor_sync(0xFFFFFFFFu, s,  o);
        s2 += __shfl_xor_sync(0xFFFFFFFFu, s2, o);
    }
    int wid = t >> 5, lane = t & 31;
    if (lane == 0) { red0[wid] = s; red1[wid] = s2; }
    __syncthreads();
    if (wid == 0) {
        float a  = (lane < 8) ? red0[lane] : 0.0f;
        float a2 = (lane < 8) ? red1[lane] : 0.0f;
        #pragma unroll
        for (int o = 4; o > 0; o >>= 1) {
            a  += __shfl_xor_sync(0xFFFFFFFFu, a,  o);
            a2 += __shfl_xor_sync(0xFFFFFFFFu, a2, o);
        }
        if (lane == 0) { red0[0] = a * (1.0f / DIM); red1[0] = a2 * (1.0f / DIM); }
    }
    __syncthreads();
    float mu  = red0[0];
    float var = red1[0] - mu * mu;
    float inv = rsqrtf(var + LN_EPS);

    float4 w4 = reinterpret_cast<const float4*>(w)[t];
    float4 b4 = reinterpret_cast<const float4*>(b)[t];
    __half2 h0 = __floats2half2_rn((v.x - mu) * inv * w4.x + b4.x,
                                   (v.y - mu) * inv * w4.y + b4.y);
    __half2 h1 = __floats2half2_rn((v.z - mu) * inv * w4.z + b4.z,
                                   (v.w - mu) * inv * w4.w + b4.w);
    __half2* orow = reinterpret_cast<__half2*>(out + (size_t)row * DIM);
    orow[2 * t]     = h0;
    orow[2 * t + 1] = h1;
}

// ---------------------------------------------------------------------------
// Softmax: exact fp32 -> att (in place), fp16 -> p
// ---------------------------------------------------------------------------
__global__ __launch_bounds__(256) void softmax_kernel(
    float* __restrict__ att, __half* __restrict__ pr)
{
    int row = blockIdx.x;
    float* p  = att + (size_t)row * SEQ;
    __half2* pq = reinterpret_cast<__half2*>(pr + (size_t)row * SEQ);
    int t = threadIdx.x;

    float4 v0 = reinterpret_cast<float4*>(p)[t];
    float4 v1 = reinterpret_cast<float4*>(p)[t + 256];

    float m = fmaxf(fmaxf(fmaxf(v0.x, v0.y), fmaxf(v0.z, v0.w)),
                    fmaxf(fmaxf(v1.x, v1.y), fmaxf(v1.z, v1.w)));

    __shared__ float red[32];
    #pragma unroll
    for (int o = 16; o > 0; o >>= 1)
        m = fmaxf(m, __shfl_xor_sync(0xFFFFFFFFu, m, o));
    int wid = t >> 5, lane = t & 31;
    if (lane == 0) red[wid] = m;
    __syncthreads();
    if (wid == 0) {
        float a = (lane < 8) ? red[lane] : -3.4e38f;
        #pragma unroll
        for (int o = 4; o > 0; o >>= 1)
            a = fmaxf(a, __shfl_xor_sync(0xFFFFFFFFu, a, o));
        if (lane == 0) red[0] = a;
    }
    __syncthreads();
    m = red[0];

    v0.x = __expf(v0.x - m); v0.y = __expf(v0.y - m);
    v0.z = __expf(v0.z - m); v0.w = __expf(v0.w - m);
    v1.x = __expf(v1.x - m); v1.y = __expf(v1.y - m);
    v1.z = __expf(v1.z - m); v1.w = __expf(v1.w - m);

    float s = v0.x + v0.y + v0.z + v0.w + v1.x + v1.y + v1.z + v1.w;
    #pragma unroll
    for (int o = 16; o > 0; o >>= 1)
        s += __shfl_xor_sync(0xFFFFFFFFu, s, o);
    if (lane == 0) red[wid] = s;
    __syncthreads();
    if (wid == 0) {
        float a = (lane < 8) ? red[lane] : 0.0f;
        #pragma unroll
        for (int o = 4; o > 0; o >>= 1)
            a += __shfl_xor_sync(0xFFFFFFFFu, a, o);
        if (lane == 0) red[0] = a;
    }
    __syncthreads();
    float inv = 1.0f / red[0];

    v0.x *= inv; v0.y *= inv; v0.z *= inv; v0.w *= inv;
    v1.x *= inv; v1.y *= inv; v1.z *= inv; v1.w *= inv;
    reinterpret_cast<float4*>(p)[t]       = v0;
    reinterpret_cast<float4*>(p)[t + 256] = v1;

    pq[2 * t]           = __floats2half2_rn(v0.x, v0.y);
    pq[2 * t + 1]       = __floats2half2_rn(v0.z, v0.w);
    pq[2 * (t + 256)]     = __floats2half2_rn(v1.x, v1.y);
    pq[2 * (t + 256) + 1] = __floats2half2_rn(v1.z, v1.w);
}

// ---------------------------------------------------------------------------
// Launch
// ---------------------------------------------------------------------------
extern "C" void kernel_launch(void* const* d_in, const int* in_sizes, int n_in,
                              void* d_out, int out_size)
{
    (void)in_sizes; (void)n_in; (void)out_size;
    const float* x   = (const float*)d_in[0];
    const float* wq  = (const float*)d_in[1];
    const float* bq  = (const float*)d_in[2];
    const float* wk  = (const float*)d_in[3];
    const float* bk  = (const float*)d_in[4];
    const float* wv  = (const float*)d_in[5];
    const float* bv  = (const float*)d_in[6];
    const float* lnw = (const float*)d_in[7];
    const float* lnb = (const float*)d_in[8];

    float* att = (float*)d_out;                 // [4,2048,2048]
    float* out = att + ATT_ELEMS;               // [4,2048,1024]

    __half *xn, *q, *k, *p, *vt;
    cudaGetSymbolAddress((void**)&xn, g_xn);
    cudaGetSymbolAddress((void**)&q,  g_q);
    cudaGetSymbolAddress((void**)&k,  g_k);
    cudaGetSymbolAddress((void**)&p,  g_p);
    cudaGetSymbolAddress((void**)&vt, g_vt);

    cudaFuncSetAttribute(qkv_kernel,
        cudaFuncAttributeMaxDynamicSharedMemorySize, GEMM_SMEM_BYTES);
    cudaFuncSetAttribute(scores_kernel,
        cudaFuncAttributeMaxDynamicSharedMemorySize, GEMM_SMEM_BYTES);
    cudaFuncSetAttribute(attv_kernel,
        cudaFuncAttributeMaxDynamicSharedMemorySize, GEMM_SMEM_BYTES);

    // 0) W^T -> fp16
    transpose_w_kernel<<<dim3(32, 32, 3), dim3(32, 8)>>>(wq, wk, wv);

    // 1) LayerNorm -> fp16 xn
    ln_kernel<<<MROWS, 256>>>(x, lnw, lnb, xn);

    // 2) QKV: 1536 tiles, one per CTA (V tiles first)
    qkv_kernel<<<1536, GTHREADS, GEMM_SMEM_BYTES>>>(xn, bq, bk, bv, q, k, vt);

    // 3) Scores: 1024 tiles, one per CTA
    scores_kernel<<<1024, GTHREADS, GEMM_SMEM_BYTES>>>(q, k, att);

    // 4) Softmax (exact fp32 -> att, fp16 -> p)
    softmax_kernel<<<MROWS, 256>>>(att, p);

    // 5) att@V: 512 tiles, one per CTA
    attv_kernel<<<512, GTHREADS, GEMM_SMEM_BYTES>>>(p, vt, out);
}

// round 17
// speedup vs baseline: 1.0331x; 1.0114x over previous
#include <cuda_runtime.h>
#include <cuda_fp16.h>
#include <cstdint>

#define BATCH 4
#define SEQ   2048
#define DIM   1024
#define MROWS (BATCH * SEQ)                    // 8192
#define ATT_ELEMS ((size_t)BATCH * SEQ * SEQ)  // 16,777,216
#define LN_EPS 1e-5f

// ---------------------------------------------------------------------------
// Scratch (device globals; no allocation allowed anywhere)
// ---------------------------------------------------------------------------
__device__ __align__(256) __half g_xn[MROWS * DIM];
__device__ __align__(256) __half g_q [MROWS * DIM];
__device__ __align__(256) __half g_k [MROWS * DIM];
__device__ __align__(256) __half g_p [ATT_ELEMS];              // fp16 probs
__device__ __align__(256) __half g_wt[3][DIM * DIM];           // W^T fp16 [h][d]
__device__ __align__(256) __half g_vt[(size_t)BATCH * DIM * SEQ]; // V^T [h][n]

// ---------------------------------------------------------------------------
// Helpers
// ---------------------------------------------------------------------------
__device__ __forceinline__ void cp16_s(uint32_t saddr, const void* gmem) {
    asm volatile("cp.async.cg.shared.global [%0], [%1], 16;\n"
                 :: "r"(saddr), "l"(gmem));
}
#define CP_COMMIT() asm volatile("cp.async.commit_group;\n")
#define CP_WAIT(N)  asm volatile("cp.async.wait_group %0;\n" :: "n"(N))

__device__ __forceinline__ void ldsm_x4(
    uint32_t& r0, uint32_t& r1, uint32_t& r2, uint32_t& r3, uint32_t a)
{
    asm volatile("ldmatrix.sync.aligned.m8n8.x4.shared.b16 {%0,%1,%2,%3}, [%4];"
                 : "=r"(r0), "=r"(r1), "=r"(r2), "=r"(r3) : "r"(a));
}
__device__ __forceinline__ void mma16816(
    float* c, const uint32_t* a, const uint32_t* b)
{
    asm volatile(
        "mma.sync.aligned.m16n8k16.row.col.f32.f16.f16.f32 "
        "{%0,%1,%2,%3}, {%4,%5,%6,%7}, {%8,%9}, {%0,%1,%2,%3};"
        : "+f"(c[0]), "+f"(c[1]), "+f"(c[2]), "+f"(c[3])
        : "r"(a[0]), "r"(a[1]), "r"(a[2]), "r"(a[3]), "r"(b[0]), "r"(b[1]));
}

#define SWZ(off) ((off) ^ (((off) >> 3) & 0x70))

// ---------------------------------------------------------------------------
// FP16 mma.sync GEMM tile: C[128,128] = scale*(A@B^T)(+bias)
//   A: [M,K] K-major halves (lda);  B: [N,K] K-major halves (ldb).
//   BK=64 halves (128B rows, SW128), 3-stage cp.async, 128 thr,
//   4 warps (2M x 2N), warp tile 64x64.
//   LDSM addressing: raw per-lane offset has bits 5-6 == 0; its swizzle XOR
//   mask depends only on bits 7-9 (invariant under +ks*32 and +s*STG_B).
//   Address = (unswizzled_base + stage_off + ks*32) ^ mask (XOR applied last).
//   TRANS: OutT must be __half; result written TRANSPOSED into Cb (V^T path),
//   with fully-coalesced row writes (16 lanes per 256B row).
// ---------------------------------------------------------------------------
#define TCBM 128
#define TCBN 128
#define TCKT 64
#define NSTG 3
#define ATILE_B (TCBM * 128)              // 16384 bytes
#define BTILE_B (TCBN * 128)              // 16384 bytes
#define STG_B   (ATILE_B + BTILE_B)       // 32768
#define GEMM_SMEM_BYTES (NSTG * STG_B)    // 98304
#define GTHREADS 128
#define LDT 136                           // padded transpose-stage row (halves)

template <bool HAS_BIAS, bool TRANS, typename OutT>
__device__ __forceinline__ void tc_gemm_tile(
    const __half* __restrict__ Ab, const __half* __restrict__ Bb,
    OutT* __restrict__ Cb, const float* __restrict__ bias,
    int K, int lda, int ldb, int ldc, float scale, int bm, int bn)
{
    extern __shared__ char smem[];
    uint32_t sb = (uint32_t)__cvta_generic_to_shared(smem);

    int tid = threadIdx.x, wid = tid >> 5, lane = tid & 31;
    int warpM = wid & 1;            // 0..1  (64 rows)
    int warpN = wid >> 1;           // 0..1  (64 cols)

    int a_row = lane & 15;
    int a_c16 = (lane >> 4) * 16;
    int b_row = (lane & 7) + ((lane >> 4) & 1) * 8;
    int b_c16 = ((lane >> 3) & 1) * 16;

    // Hoisted unswizzled bases + XOR masks.
    uint32_t a_base[4], a_mask[4], b_base[4], b_mask[4];
    #pragma unroll
    for (int mi = 0; mi < 4; mi++) {
        uint32_t off = (uint32_t)((warpM * 64 + mi * 16 + a_row) * 128 + a_c16);
        a_mask[mi] = (off >> 3) & 0x70;
        a_base[mi] = sb + off;
    }
    #pragma unroll
    for (int nj = 0; nj < 4; nj++) {
        uint32_t off = (uint32_t)((warpN * 64 + nj * 16 + b_row) * 128 + b_c16);
        b_mask[nj] = (off >> 3) & 0x70;
        b_base[nj] = sb + ATILE_B + off;
    }

    auto load_stage = [&](uint32_t soff, int k0) {
        uint32_t abase = sb + soff;
        uint32_t bbase = abase + ATILE_B;
        #pragma unroll
        for (int i = 0; i < 8; i++) {            // A: 1024 16B chunks
            int c = tid + i * GTHREADS;
            int r = c >> 3, col = c & 7;
            uint32_t off = (uint32_t)(r * 128 + col * 16);
            cp16_s(abase + SWZ(off),
                   Ab + (size_t)(bm + r) * lda + k0 + col * 8);
        }
        #pragma unroll
        for (int i = 0; i < 8; i++) {            // B: 1024 16B chunks
            int c = tid + i * GTHREADS;
            int r = c >> 3, col = c & 7;
            uint32_t off = (uint32_t)(r * 128 + col * 16);
            cp16_s(bbase + SWZ(off),
                   Bb + (size_t)(bn + r) * ldb + k0 + col * 8);
        }
    };

    float acc[4][8][4];
    #pragma unroll
    for (int mi = 0; mi < 4; mi++)
        #pragma unroll
        for (int ni = 0; ni < 8; ni++)
            #pragma unroll
            for (int e = 0; e < 4; e++)
                acc[mi][ni][e] = 0.0f;

    int NT = K / TCKT;

    load_stage(0, 0);
    CP_COMMIT();
    load_stage(STG_B, TCKT);
    CP_COMMIT();

    uint32_t stg_off = 0;                        // current stage offset
    uint32_t ld_off  = 2 * STG_B;                // next load slot offset
    int k0_next = 2 * TCKT;                      // next load k origin

    for (int kt = 0; kt < NT; kt++) {
        CP_WAIT(1);
        __syncthreads();

        if (kt + 2 < NT) load_stage(ld_off, k0_next);
        CP_COMMIT();
        ld_off = (ld_off == (NSTG - 1) * STG_B) ? 0u : ld_off + STG_B;
        k0_next += TCKT;

        uint32_t cur = stg_off;
        stg_off = (stg_off == (NSTG - 1) * STG_B) ? 0u : stg_off + STG_B;

        #pragma unroll
        for (int ks = 0; ks < 4; ks++) {         // 4 x k16 = K-tile 64
            uint32_t a[4][4], b[8][2];
            #pragma unroll
            for (int mi = 0; mi < 4; mi++)
                ldsm_x4(a[mi][0], a[mi][1], a[mi][2], a[mi][3],
                        (a_base[mi] + cur + ks * 32) ^ a_mask[mi]);
            #pragma unroll
            for (int nj = 0; nj < 4; nj++)
                ldsm_x4(b[2 * nj][0], b[2 * nj][1],
                        b[2 * nj + 1][0], b[2 * nj + 1][1],
                        (b_base[nj] + cur + ks * 32) ^ b_mask[nj]);
            #pragma unroll
            for (int mi = 0; mi < 4; mi++)
                #pragma unroll
                for (int ni = 0; ni < 8; ni++)
                    mma16816(acc[mi][ni], a[mi], b[ni]);
        }
    }

    int g = lane >> 2, t = lane & 3;

    if constexpr (TRANS) {
        // Stage result in smem transposed ([col][row], padded), then write
        // coalesced rows of V^T (16 consecutive lanes cover one 256B row).
        __half* st = reinterpret_cast<__half*>(smem);
        __syncthreads();   // smem stages are dead; safe to reuse
        #pragma unroll
        for (int mi = 0; mi < 4; mi++) {
            int r0 = warpM * 64 + mi * 16 + g;
            #pragma unroll
            for (int ni = 0; ni < 8; ni++) {
                int col = warpN * 64 + ni * 8 + 2 * t;
                float v0 = acc[mi][ni][0] * scale;
                float v1 = acc[mi][ni][1] * scale;
                float v2 = acc[mi][ni][2] * scale;
                float v3 = acc[mi][ni][3] * scale;
                if (HAS_BIAS) {
                    float b0 = bias[bn + col], b1 = bias[bn + col + 1];
                    v0 += b0; v1 += b1; v2 += b0; v3 += b1;
                }
                st[col * LDT + r0]           = __float2half_rn(v0);
                st[(col + 1) * LDT + r0]     = __float2half_rn(v1);
                st[col * LDT + r0 + 8]       = __float2half_rn(v2);
                st[(col + 1) * LDT + r0 + 8] = __float2half_rn(v3);
            }
        }
        __syncthreads();
        // 2048 16B chunks total (128 rows x 16 chunks). chunk c = tid + i*128:
        // row = c>>4, ch = c&15 -> consecutive lanes hit consecutive 16B
        // chunks within one row (coalesced 256B segments).
        int b = bm >> 11;                 // SEQ = 2048
        int nb = bm & (SEQ - 1);
        __half* base = (__half*)Cb + ((size_t)b * DIM + bn) * SEQ + nb;
        #pragma unroll
        for (int i = 0; i < 16; i++) {
            int c = tid + i * GTHREADS;
            int row = c >> 4, ch = c & 15;
            *reinterpret_cast<uint4*>(base + (size_t)row * SEQ + ch * 8) =
                *reinterpret_cast<const uint4*>(st + row * LDT + ch * 8);
        }
        return;
    }

    // Register epilogue: c0,c1 -> (row g, col 2t); c2,c3 -> (row g+8)
    #pragma unroll
    for (int mi = 0; mi < 4; mi++) {
        int r0 = bm + warpM * 64 + mi * 16 + g;
        #pragma unroll
        for (int ni = 0; ni < 8; ni++) {
            int col = bn + warpN * 64 + ni * 8 + 2 * t;
            float2 lo, hi;
            lo.x = acc[mi][ni][0] * scale; lo.y = acc[mi][ni][1] * scale;
            hi.x = acc[mi][ni][2] * scale; hi.y = acc[mi][ni][3] * scale;
            if (HAS_BIAS) {
                float b0 = bias[col], b1 = bias[col + 1];
                lo.x += b0; lo.y += b1; hi.x += b0; hi.y += b1;
            }
            if (sizeof(OutT) == 2) {
                *reinterpret_cast<__half2*>(
                    (__half*)Cb + (size_t)r0 * ldc + col) =
                    __floats2half2_rn(lo.x, lo.y);
                *reinterpret_cast<__half2*>(
                    (__half*)Cb + (size_t)(r0 + 8) * ldc + col) =
                    __floats2half2_rn(hi.x, hi.y);
            } else {
                *reinterpret_cast<float2*>(
                    (float*)Cb + (size_t)r0 * ldc + col) = lo;
                *reinterpret_cast<float2*>(
                    (float*)Cb + (size_t)(r0 + 8) * ldc + col) = hi;
            }
        }
    }
}

// ---------------------------------------------------------------------------
// GEMM kernels: one tile per CTA (hardware scheduler balances SM load)
// ---------------------------------------------------------------------------
__global__ __launch_bounds__(GTHREADS, 2) void qkv_kernel(
    const __half* __restrict__ xn,
    const float* __restrict__ b0, const float* __restrict__ b1,
    const float* __restrict__ b2,
    __half* q, __half* k, __half* vt)
{
    const int TPM = MROWS / TCBM;      // 64
    const int TPN = DIM / TCBN;        // 8
    const int TPZ = TPM * TPN;         // 512
    int t = blockIdx.x;                // 0..1535; order: V(0..511), Q, K
    int zz = t / TPZ, rem = t - zz * TPZ;
    int bm = (rem / TPN) * TCBM;
    int bn = (rem - (rem / TPN) * TPN) * TCBN;
    if (zz == 0) {
        tc_gemm_tile<true, true, __half>(xn, g_wt[2], vt, b2,
                                         DIM, DIM, DIM, SEQ, 1.0f, bm, bn);
    } else if (zz == 1) {
        tc_gemm_tile<true, false, __half>(xn, g_wt[0], q, b0,
                                          DIM, DIM, DIM, DIM, 1.0f, bm, bn);
    } else {
        tc_gemm_tile<true, false, __half>(xn, g_wt[1], k, b1,
                                          DIM, DIM, DIM, DIM, 1.0f, bm, bn);
    }
}

__global__ __launch_bounds__(GTHREADS, 2) void scores_kernel(
    const __half* __restrict__ q, const __half* __restrict__ k,
    float* __restrict__ att)
{
    const int TPM = SEQ / TCBM;        // 16
    const int TPN = SEQ / TCBN;        // 16
    const int TPZ = TPM * TPN;         // 256
    int t = blockIdx.x;                // 0..1023
    int z = t / TPZ, rem = t - z * TPZ;
    int bm = (rem / TPN) * TCBM;
    int bn = (rem - (rem / TPN) * TPN) * TCBN;
    size_t zo = (size_t)z * SEQ * DIM;
    float* Cb = att + (size_t)z * SEQ * SEQ;
    tc_gemm_tile<false, false, float>(q + zo, k + zo, Cb, nullptr,
                                      DIM, DIM, DIM, SEQ, 1.0f / 32.0f,
                                      bm, bn);
}

__global__ __launch_bounds__(GTHREADS, 2) void attv_kernel(
    const __half* __restrict__ p, const __half* __restrict__ vt,
    float* __restrict__ out)
{
    const int TPM = SEQ / TCBM;        // 16
    const int TPN = DIM / TCBN;        // 8
    const int TPZ = TPM * TPN;         // 128
    int t = blockIdx.x;                // 0..511
    int z = t / TPZ, rem = t - z * TPZ;
    int bm = (rem / TPN) * TCBM;
    int bn = (rem - (rem / TPN) * TPN) * TCBN;
    const __half* Ab = p  + (size_t)z * SEQ * SEQ;
    const __half* Bb = vt + (size_t)z * DIM * SEQ;
    float* Cb = out + (size_t)z * SEQ * DIM;
    tc_gemm_tile<false, false, float>(Ab, Bb, Cb, nullptr,
                                      SEQ, SEQ, SEQ, DIM, 1.0f, bm, bn);
}

// ---------------------------------------------------------------------------
// W transpose (fp32 [d][h] -> fp16 [h][d])
// ---------------------------------------------------------------------------
__global__ __launch_bounds__(256) void transpose_w_kernel(
    const float* __restrict__ w0, const float* __restrict__ w1,
    const float* __restrict__ w2)
{
    __shared__ float t[32][33];
    int z = blockIdx.z;
    const float* src = (z == 0) ? w0 : (z == 1) ? w1 : w2;  // [d][h]
    __half* dst = g_wt[z];                                  // [h][d]
    int c0 = blockIdx.x * 32;   // h
    int r0 = blockIdx.y * 32;   // d
    int tx = threadIdx.x, ty = threadIdx.y;
    #pragma unroll
    for (int j = 0; j < 4; j++)
        t[ty + j * 8][tx] = src[(size_t)(r0 + ty + j * 8) * DIM + c0 + tx];
    __syncthreads();
    #pragma unroll
    for (int j = 0; j < 4; j++)
        dst[(size_t)(c0 + ty + j * 8) * DIM + r0 + tx] =
            __float2half_rn(t[tx][ty + j * 8]);
}

// ---------------------------------------------------------------------------
// LayerNorm (outputs fp16)
// ---------------------------------------------------------------------------
__global__ __launch_bounds__(256) void ln_kernel(
    const float* __restrict__ x, const float* __restrict__ w,
    const float* __restrict__ b, __half* __restrict__ out)
{
    int row = blockIdx.x;
    int t = threadIdx.x;
    const float4* xr = reinterpret_cast<const float4*>(x + (size_t)row * DIM);
    float4 v = xr[t];

    float s  = v.x + v.y + v.z + v.w;
    float s2 = v.x * v.x + v.y * v.y + v.z * v.z + v.w * v.w;

    __shared__ float red0[32], red1[32];
    #pragma unroll
    for (int o = 16; o > 0; o >>= 1) {
        s  += __shfl_xor_sync(0xFFFFFFFFu, s,  o);
        s2 += __shfl_xor_sync(0xFFFFFFFFu, s2, o);
    }
    int wid = t >> 5, lane = t & 31;
    if (lane == 0) { red0[wid] = s; red1[wid] = s2; }
    __syncthreads();
    if (wid == 0) {
        float a  = (lane < 8) ? red0[lane] : 0.0f;
        float a2 = (lane < 8) ? red1[lane] : 0.0f;
        #pragma unroll
        for (int o = 4; o > 0; o >>= 1) {
            a  += __shfl_xor_sync(0xFFFFFFFFu, a,  o);
            a2 += __shfl_xor_sync(0xFFFFFFFFu, a2, o);
        }
        if (lane == 0) { red0[0] = a * (1.0f / DIM); red1[0] = a2 * (1.0f / DIM); }
    }
    __syncthreads();
    float mu  = red0[0];
    float var = red1[0] - mu * mu;
    float inv = rsqrtf(var + LN_EPS);

    float4 w4 = reinterpret_cast<const float4*>(w)[t];
    float4 b4 = reinterpret_cast<const float4*>(b)[t];
    __half2 h0 = __floats2half2_rn((v.x - mu) * inv * w4.x + b4.x,
                                   (v.y - mu) * inv * w4.y + b4.y);
    __half2 h1 = __floats2half2_rn((v.z - mu) * inv * w4.z + b4.z,
                                   (v.w - mu) * inv * w4.w + b4.w);
    __half2* orow = reinterpret_cast<__half2*>(out + (size_t)row * DIM);
    orow[2 * t]     = h0;
    orow[2 * t + 1] = h1;
}

// ---------------------------------------------------------------------------
// Softmax: exact fp32 -> att (in place), fp16 -> p
// ---------------------------------------------------------------------------
__global__ __launch_bounds__(256) void softmax_kernel(
    float* __restrict__ att, __half* __restrict__ pr)
{
    int row = blockIdx.x;
    float* p  = att + (size_t)row * SEQ;
    __half2* pq = reinterpret_cast<__half2*>(pr + (size_t)row * SEQ);
    int t = threadIdx.x;

    float4 v0 = reinterpret_cast<float4*>(p)[t];
    float4 v1 = reinterpret_cast<float4*>(p)[t + 256];

    float m = fmaxf(fmaxf(fmaxf(v0.x, v0.y), fmaxf(v0.z, v0.w)),
                    fmaxf(fmaxf(v1.x, v1.y), fmaxf(v1.z, v1.w)));

    __shared__ float red[32];
    #pragma unroll
    for (int o = 16; o > 0; o >>= 1)
        m = fmaxf(m, __shfl_xor_sync(0xFFFFFFFFu, m, o));
    int wid = t >> 5, lane = t & 31;
    if (lane == 0) red[wid] = m;
    __syncthreads();
    if (wid == 0) {
        float a = (lane < 8) ? red[lane] : -3.4e38f;
        #pragma unroll
        for (int o = 4; o > 0; o >>= 1)
            a = fmaxf(a, __shfl_xor_sync(0xFFFFFFFFu, a, o));
        if (lane == 0) red[0] = a;
    }
    __syncthreads();
    m = red[0];

    v0.x = __expf(v0.x - m); v0.y = __expf(v0.y - m);
    v0.z = __expf(v0.z - m); v0.w = __expf(v0.w - m);
    v1.x = __expf(v1.x - m); v1.y = __expf(v1.y - m);
    v1.z = __expf(v1.z - m); v1.w = __expf(v1.w - m);

    float s = v0.x + v0.y + v0.z + v0.w + v1.x + v1.y + v1.z + v1.w;
    #pragma unroll
    for (int o = 16; o > 0; o >>= 1)
        s += __shfl_xor_sync(0xFFFFFFFFu, s, o);
    if (lane == 0) red[wid] = s;
    __syncthreads();
    if (wid == 0) {
        float a = (lane < 8) ? red[lane] : 0.0f;
        #pragma unroll
        for (int o = 4; o > 0; o >>= 1)
            a += __shfl_xor_sync(0xFFFFFFFFu, a, o);
        if (lane == 0) red[0] = a;
    }
    __syncthreads();
    float inv = 1.0f / red[0];

    v0.x *= inv; v0.y *= inv; v0.z *= inv; v0.w *= inv;
    v1.x *= inv; v1.y *= inv; v1.z *= inv; v1.w *= inv;
    reinterpret_cast<float4*>(p)[t]       = v0;
    reinterpret_cast<float4*>(p)[t + 256] = v1;

    pq[2 * t]           = __floats2half2_rn(v0.x, v0.y);
    pq[2 * t + 1]       = __floats2half2_rn(v0.z, v0.w);
    pq[2 * (t + 256)]     = __floats2half2_rn(v1.x, v1.y);
    pq[2 * (t + 256) + 1] = __floats2half2_rn(v1.z, v1.w);
}

// ---------------------------------------------------------------------------
// Launch
// ---------------------------------------------------------------------------
extern "C" void kernel_launch(void* const* d_in, const int* in_sizes, int n_in,
                              void* d_out, int out_size)
{
    (void)in_sizes; (void)n_in; (void)out_size;
    const float* x   = (const float*)d_in[0];
    const float* wq  = (const float*)d_in[1];
    const float* bq  = (const float*)d_in[2];
    const float* wk  = (const float*)d_in[3];
    const float* bk  = (const float*)d_in[4];
    const float* wv  = (const float*)d_in[5];
    const float* bv  = (const float*)d_in[6];
    const float* lnw = (const float*)d_in[7];
    const float* lnb = (const float*)d_in[8];

    float* att = (float*)d_out;                 // [4,2048,2048]
    float* out = att + ATT_ELEMS;               // [4,2048,1024]

    __half *xn, *q, *k, *p, *vt;
    cudaGetSymbolAddress((void**)&xn, g_xn);
    cudaGetSymbolAddress((void**)&q,  g_q);
    cudaGetSymbolAddress((void**)&k,  g_k);
    cudaGetSymbolAddress((void**)&p,  g_p);
    cudaGetSymbolAddress((void**)&vt, g_vt);

    cudaFuncSetAttribute(qkv_kernel,
        cudaFuncAttributeMaxDynamicSharedMemorySize, GEMM_SMEM_BYTES);
    cudaFuncSetAttribute(scores_kernel,
        cudaFuncAttributeMaxDynamicSharedMemorySize, GEMM_SMEM_BYTES);
    cudaFuncSetAttribute(attv_kernel,
        cudaFuncAttributeMaxDynamicSharedMemorySize, GEMM_SMEM_BYTES);

    // 0) W^T -> fp16
    transpose_w_kernel<<<dim3(32, 32, 3), dim3(32, 8)>>>(wq, wk, wv);

    // 1) LayerNorm -> fp16 xn
    ln_kernel<<<MROWS, 256>>>(x, lnw, lnb, xn);

    // 2) QKV: 1536 tiles, one per CTA (V tiles first)
    qkv_kernel<<<1536, GTHREADS, GEMM_SMEM_BYTES>>>(xn, bq, bk, bv, q, k, vt);

    // 3) Scores: 1024 tiles, one per CTA
    scores_kernel<<<1024, GTHREADS, GEMM_SMEM_BYTES>>>(q, k, att);

    // 4) Softmax (exact fp32 -> att, fp16 -> p)
    softmax_kernel<<<MROWS, 256>>>(att, p);

    // 5) att@V: 512 tiles, one per CTA
    attv_kernel<<<512, GTHREADS, GEMM_SMEM_BYTES>>>(p, vt, out);
}